// round 1
// baseline (speedup 1.0000x reference)
#include <cuda_runtime.h>
#include <cuda_bf16.h>
#include <math.h>

// Problem dims
#define NN 768
#define XD 768
#define HID 300
#define HP 304      // padded hidden (multiple of 16)
#define W1COLS 1536 // X_DIM + Y_DIM

// Scratch (device globals -- no allocation allowed)
__device__ float g_hxT[HP * NN];  // [h][n] : hx transposed (cT), rows 300..303 zeroed
__device__ float g_hyT[HP * NN];  // [h][n] : hy transposed
__device__ float g_aT[HP * NN];   // [h][i] : hy[perm[i]][h] + b1[h], padded rows zero
__device__ float g_w2p[HP];       // padded w2
__device__ float g_t1[NN * NN];   // softplus(t1) matrix
__device__ float g_t0[NN];
__device__ float g_lse[NN];

// ---------------------------------------------------------------------------
// GEMM: outT[h][n] = sum_k S[n][k] * W1[h][wofs + k]   (h < 300)
// block 16x16 threads, 64x64 tile, 4x4 micro-tile, k-chunk 16
// ---------------------------------------------------------------------------
__global__ void gemm_hT(const float* __restrict__ S, const float* __restrict__ W1,
                        int which /*0: hxT, 1: hyT*/, int wofs) {
    __shared__ float sS[16][68]; // [k][n], padded (272B rows, 16B aligned)
    __shared__ float sW[16][68]; // [k][h]
    float* outT = which ? g_hyT : g_hxT;

    const int n0 = blockIdx.x * 64;
    const int h0 = blockIdx.y * 64;
    const int tx = threadIdx.x, ty = threadIdx.y;
    const int tid = ty * 16 + tx;

    float acc[4][4] = {};

    for (int k0 = 0; k0 < XD; k0 += 16) {
        // Load S tile: 64 n-rows x 16 k-cols (coalesced along k, float4)
        {
            const int r = tid >> 2;          // 0..63 (n within tile)
            const int c = (tid & 3) * 4;     // 0,4,8,12 (k within chunk)
            float4 v = *(const float4*)&S[(size_t)(n0 + r) * XD + k0 + c];
            sS[c + 0][r] = v.x; sS[c + 1][r] = v.y;
            sS[c + 2][r] = v.z; sS[c + 3][r] = v.w;
        }
        // Load W tile: 64 h-rows x 16 k-cols, guard h < 300
        {
            const int r = tid >> 2;          // h within tile
            const int c = (tid & 3) * 4;
            const int h = h0 + r;
            float4 v = make_float4(0.f, 0.f, 0.f, 0.f);
            if (h < HID) v = *(const float4*)&W1[(size_t)h * W1COLS + wofs + k0 + c];
            sW[c + 0][r] = v.x; sW[c + 1][r] = v.y;
            sW[c + 2][r] = v.z; sW[c + 3][r] = v.w;
        }
        __syncthreads();

        #pragma unroll
        for (int kk = 0; kk < 16; kk++) {
            float a[4], b[4];
            #pragma unroll
            for (int p = 0; p < 4; p++) a[p] = sW[kk][ty * 4 + p];
            #pragma unroll
            for (int q = 0; q < 4; q++) b[q] = sS[kk][tx * 4 + q];
            #pragma unroll
            for (int p = 0; p < 4; p++)
                #pragma unroll
                for (int q = 0; q < 4; q++)
                    acc[p][q] = fmaf(a[p], b[q], acc[p][q]);
        }
        __syncthreads();
    }

    #pragma unroll
    for (int p = 0; p < 4; p++) {
        const int h = h0 + ty * 4 + p;
        if (h < HID) {
            float4 v = make_float4(acc[p][0], acc[p][1], acc[p][2], acc[p][3]);
            *(float4*)&outT[(size_t)h * NN + n0 + tx * 4] = v;
        }
    }
}

// ---------------------------------------------------------------------------
// Prep: aT[h][i] = hyT[h][perm[i]] + b1[h] (h<300), zero pads, padded w2.
// Also zero pad rows of hxT (cT).
// ---------------------------------------------------------------------------
__global__ void prep_kernel(const int* __restrict__ perm,
                            const float* __restrict__ b1,
                            const float* __restrict__ W2) {
    const int idx = blockIdx.x * 256 + threadIdx.x;
    if (idx < HP * NN) {
        const int h = idx / NN;
        const int i = idx - h * NN;
        float v = 0.f;
        if (h < HID) v = g_hyT[(size_t)h * NN + perm[i]] + b1[h];
        g_aT[idx] = v;
        if (h >= HID) g_hxT[idx] = 0.f;  // zero pad of c tiles
    }
    if (idx < HP) g_w2p[idx] = (idx < HID) ? W2[idx] : 0.f;
}

__device__ __forceinline__ float softplus_f(float z) {
    return fmaxf(z, 0.f) + log1pf(expf(-fabsf(z)));
}

// ---------------------------------------------------------------------------
// t0[n] = softplus( sum_h w2[h]*relu(hx[n][h]+hy[n][h]+b1[h]) + b2 )
// ---------------------------------------------------------------------------
__global__ void t0_kernel(const float* __restrict__ b1,
                          const float* __restrict__ W2,
                          const float* __restrict__ b2) {
    const int n = blockIdx.x * 256 + threadIdx.x;
    if (n >= NN) return;
    float s = 0.f;
    for (int h = 0; h < HID; h++) {
        float v = g_hxT[(size_t)h * NN + n] + g_hyT[(size_t)h * NN + n] + b1[h];
        s = fmaf(W2[h], fmaxf(v, 0.f), s);
    }
    g_t0[n] = softplus_f(s + b2[0]);
}

// ---------------------------------------------------------------------------
// Pairwise: t1[i][j] = softplus( sum_h w2[h]*relu(aT[h][i]+cT[h][j]) + b2 )
// 64x64 (i,j) tile per CTA; 16x16 threads; 4x4 micro-tile; h staged by 16.
// ---------------------------------------------------------------------------
__global__ void pair_kernel(const float* __restrict__ b2) {
    __shared__ float sA[16][64];
    __shared__ float sC[16][64];
    __shared__ float sw[16];

    const int i0 = blockIdx.y * 64;
    const int j0 = blockIdx.x * 64;
    const int tx = threadIdx.x, ty = threadIdx.y;
    const int tid = ty * 16 + tx;

    float acc[4][4] = {};

    for (int h0 = 0; h0 < HP; h0 += 16) {
        {
            const int r = tid >> 4;          // h within chunk, 0..15
            const int c = (tid & 15) * 4;    // 0..60
            *(float4*)&sA[r][c] = *(const float4*)&g_aT[(size_t)(h0 + r) * NN + i0 + c];
            *(float4*)&sC[r][c] = *(const float4*)&g_hxT[(size_t)(h0 + r) * NN + j0 + c];
            if (tid < 16) sw[tid] = g_w2p[h0 + tid];
        }
        __syncthreads();

        #pragma unroll
        for (int hh = 0; hh < 16; hh++) {
            const float w = sw[hh];
            float a[4], c4[4];
            *(float4*)a  = *(const float4*)&sA[hh][ty * 4];
            *(float4*)c4 = *(const float4*)&sC[hh][tx * 4];
            #pragma unroll
            for (int p = 0; p < 4; p++)
                #pragma unroll
                for (int q = 0; q < 4; q++)
                    acc[p][q] = fmaf(w, fmaxf(a[p] + c4[q], 0.f), acc[p][q]);
        }
        __syncthreads();
    }

    const float bb = b2[0];
    #pragma unroll
    for (int p = 0; p < 4; p++) {
        float4 v;
        v.x = softplus_f(acc[p][0] + bb);
        v.y = softplus_f(acc[p][1] + bb);
        v.z = softplus_f(acc[p][2] + bb);
        v.w = softplus_f(acc[p][3] + bb);
        *(float4*)&g_t1[(size_t)(i0 + ty * 4 + p) * NN + j0 + tx * 4] = v;
    }
}

// ---------------------------------------------------------------------------
// Row-wise logsumexp over j (deterministic tree reductions)
// ---------------------------------------------------------------------------
__global__ void lse_kernel() {
    __shared__ float red[256];
    const int i = blockIdx.x;
    const int t = threadIdx.x;
    const float* row = &g_t1[(size_t)i * NN];

    float m = -INFINITY;
    for (int j = t; j < NN; j += 256) m = fmaxf(m, row[j]);
    red[t] = m; __syncthreads();
    for (int s = 128; s > 0; s >>= 1) {
        if (t < s) red[t] = fmaxf(red[t], red[t + s]);
        __syncthreads();
    }
    m = red[0]; __syncthreads();

    float s = 0.f;
    for (int j = t; j < NN; j += 256) s += expf(row[j] - m);
    red[t] = s; __syncthreads();
    for (int st = 128; st > 0; st >>= 1) {
        if (t < st) red[t] += red[t + st];
        __syncthreads();
    }
    if (t == 0) g_lse[i] = m + logf(red[0]);
}

__global__ void final_kernel(float* __restrict__ out) {
    __shared__ float r0[256], r1[256];
    const int t = threadIdx.x;
    float s0 = 0.f, s1 = 0.f;
    for (int i = t; i < NN; i += 256) { s0 += g_t0[i]; s1 += g_lse[i]; }
    r0[t] = s0; r1[t] = s1; __syncthreads();
    for (int s = 128; s > 0; s >>= 1) {
        if (t < s) { r0[t] += r0[t + s]; r1[t] += r1[t + s]; }
        __syncthreads();
    }
    if (t == 0) {
        float mean_t0  = r0[0] / (float)NN;
        float mean_lse = r1[0] / (float)NN;
        out[0] = mean_t0 - (mean_lse - logf((float)NN));
    }
}

// ---------------------------------------------------------------------------
// Inputs (metadata order): x_samples, y_samples, perm, W1, b1, W2, b2
// ---------------------------------------------------------------------------
extern "C" void kernel_launch(void* const* d_in, const int* in_sizes, int n_in,
                              void* d_out, int out_size) {
    const float* x    = (const float*)d_in[0];
    const float* y    = (const float*)d_in[1];
    const int*   perm = (const int*)d_in[2];
    const float* W1   = (const float*)d_in[3];
    const float* b1   = (const float*)d_in[4];
    const float* W2   = (const float*)d_in[5];
    const float* b2   = (const float*)d_in[6];
    float* out = (float*)d_out;

    dim3 gblk(16, 16);
    dim3 ggrid(NN / 64, (HID + 63) / 64);   // 12 x 5
    gemm_hT<<<ggrid, gblk>>>(x, W1, 0, 0);
    gemm_hT<<<ggrid, gblk>>>(y, W1, 1, XD);

    prep_kernel<<<(HP * NN + 255) / 256, 256>>>(perm, b1, W2);

    t0_kernel<<<(NN + 255) / 256, 256>>>(b1, W2, b2);

    dim3 pgrid(NN / 64, NN / 64);           // 12 x 12
    pair_kernel<<<pgrid, gblk>>>(b2);

    lse_kernel<<<NN, 256>>>();
    final_kernel<<<1, 256>>>(out);
}

// round 3
// speedup vs baseline: 1.5973x; 1.5973x over previous
#include <cuda_runtime.h>
#include <cuda_bf16.h>
#include <math.h>

#define NN 768
#define XD 768
#define HID 300
#define HP 304
#define W1COLS 1536

typedef unsigned long long ull;

// Scratch (device globals -- no allocation allowed)
__device__ float g_hxT[HP * NN];     // [h][n] hx^T ("c" side), rows >=300 zeroed by prep
__device__ float g_hyT[HP * NN];     // [h][n] hy^T
__device__ ull   g_aT2[HP * NN];     // [h][i] {a,a} dup, a = hy[perm i][h] + b1[h]
__device__ ull   g_w2dup[HP];        // {w,w}, 0 for h>=HID
__device__ float g_Ai[NN];           // sum_h w*a_hi
__device__ float g_Cj[NN];           // sum_h w*c_hj
__device__ float g_t1[NN * NN];      // softplus(t1)
__device__ float g_t0[NN];
__device__ float g_lse[NN];

__device__ __forceinline__ ull add_f32x2(ull a, ull b) {
    ull d; asm("add.rn.f32x2 %0, %1, %2;" : "=l"(d) : "l"(a), "l"(b)); return d;
}
__device__ __forceinline__ ull fma_f32x2(ull a, ull b, ull c) {
    ull d; asm("fma.rn.f32x2 %0, %1, %2, %3;" : "=l"(d) : "l"(a), "l"(b), "l"(c)); return d;
}
__device__ __forceinline__ float softplus_f(float z) {
    return fmaxf(z, 0.f) + log1pf(expf(-fabsf(z)));
}

// ---------------------------------------------------------------------------
// Fused GEMM: outT[h][n] = sum_k S[n][k] * W1[h][wofs+k]; z=0 -> hxT, z=1 -> hyT
// 64x64 tile, 16x16 threads, 4x4 micro-tile, k-chunk 32.
// ---------------------------------------------------------------------------
__global__ void gemm_hT(const float* __restrict__ x, const float* __restrict__ y,
                        const float* __restrict__ W1) {
    __shared__ float sS[32][68];
    __shared__ float sW[32][68];

    const int which = blockIdx.z;
    const float* S = which ? y : x;
    const int wofs = which ? XD : 0;
    float* outT = which ? g_hyT : g_hxT;

    const int n0 = blockIdx.x * 64;
    const int h0 = blockIdx.y * 64;
    const int tx = threadIdx.x, ty = threadIdx.y;
    const int tid = ty * 16 + tx;
    const int lr = tid >> 3;           // 0..31
    const int lc = (tid & 7) * 4;      // 0..28

    float acc[4][4] = {};

    for (int k0 = 0; k0 < XD; k0 += 32) {
        // S tile: 64 n-rows x 32 k-cols
        {
            float4 v0 = *(const float4*)&S[(size_t)(n0 + lr) * XD + k0 + lc];
            float4 v1 = *(const float4*)&S[(size_t)(n0 + lr + 32) * XD + k0 + lc];
            sS[lc + 0][lr] = v0.x; sS[lc + 1][lr] = v0.y;
            sS[lc + 2][lr] = v0.z; sS[lc + 3][lr] = v0.w;
            sS[lc + 0][lr + 32] = v1.x; sS[lc + 1][lr + 32] = v1.y;
            sS[lc + 2][lr + 32] = v1.z; sS[lc + 3][lr + 32] = v1.w;
        }
        // W tile: 64 h-rows x 32 k-cols (guard h < HID)
        {
            const int h1 = h0 + lr, h2 = h0 + lr + 32;
            float4 v0 = make_float4(0.f, 0.f, 0.f, 0.f), v1 = v0;
            if (h1 < HID) v0 = *(const float4*)&W1[(size_t)h1 * W1COLS + wofs + k0 + lc];
            if (h2 < HID) v1 = *(const float4*)&W1[(size_t)h2 * W1COLS + wofs + k0 + lc];
            sW[lc + 0][lr] = v0.x; sW[lc + 1][lr] = v0.y;
            sW[lc + 2][lr] = v0.z; sW[lc + 3][lr] = v0.w;
            sW[lc + 0][lr + 32] = v1.x; sW[lc + 1][lr + 32] = v1.y;
            sW[lc + 2][lr + 32] = v1.z; sW[lc + 3][lr + 32] = v1.w;
        }
        __syncthreads();

        #pragma unroll
        for (int kk = 0; kk < 32; kk++) {
            float4 a4 = *(const float4*)&sW[kk][ty * 4];
            float4 b4 = *(const float4*)&sS[kk][tx * 4];
            float a[4] = {a4.x, a4.y, a4.z, a4.w};
            float b[4] = {b4.x, b4.y, b4.z, b4.w};
            #pragma unroll
            for (int p = 0; p < 4; p++)
                #pragma unroll
                for (int q = 0; q < 4; q++)
                    acc[p][q] = fmaf(a[p], b[q], acc[p][q]);
        }
        __syncthreads();
    }

    #pragma unroll
    for (int p = 0; p < 4; p++) {
        const int h = h0 + ty * 4 + p;
        if (h < HID) {
            float4 v = make_float4(acc[p][0], acc[p][1], acc[p][2], acc[p][3]);
            *(float4*)&outT[(size_t)h * NN + n0 + tx * 4] = v;
        }
    }
}

// ---------------------------------------------------------------------------
// Prep: aT2[h][i] = dup(hy[perm i][h] + b1[h]); zero pads (incl. hxT rows>=300);
//       w2dup[h] = dup(w2[h]) (0 padded).
// ---------------------------------------------------------------------------
__global__ void prep_kernel(const int* __restrict__ perm,
                            const float* __restrict__ b1,
                            const float* __restrict__ W2) {
    const int idx = blockIdx.x * 256 + threadIdx.x;
    if (idx < HP * NN) {
        const int h = idx / NN;
        const int i = idx - h * NN;
        float a = 0.f;
        if (h < HID) a = g_hyT[(size_t)h * NN + perm[i]] + b1[h];
        else g_hxT[idx] = 0.f;   // pad c-side rows
        unsigned ab = __float_as_uint(a);
        g_aT2[idx] = ((ull)ab << 32) | (ull)ab;
    }
    if (idx < HP) {
        float w = (idx < HID) ? W2[idx] : 0.f;
        unsigned wb = __float_as_uint(w);
        g_w2dup[idx] = ((ull)wb << 32) | (ull)wb;
    }
}

// ---------------------------------------------------------------------------
// Stats (grid (24,3), block (32,8)): mode 0 -> t0, 1 -> A_i, 2 -> C_j
// ---------------------------------------------------------------------------
__global__ void stats_kernel(const float* __restrict__ b1,
                             const float* __restrict__ W2,
                             const float* __restrict__ b2) {
    __shared__ float red[8][33];
    const int tx = threadIdx.x, ty = threadIdx.y;
    const int n = blockIdx.x * 32 + tx;
    const int mode = blockIdx.y;

    float p = 0.f;
    if (mode == 0) {
        for (int h = ty; h < HID; h += 8) {
            float v = g_hxT[(size_t)h * NN + n] + g_hyT[(size_t)h * NN + n] + b1[h];
            p = fmaf(W2[h], fmaxf(v, 0.f), p);
        }
    } else if (mode == 1) {
        for (int h = ty; h < HID; h += 8) {
            float a = __uint_as_float((unsigned)(g_aT2[(size_t)h * NN + n] & 0xffffffffu));
            p = fmaf(W2[h], a, p);
        }
    } else {
        for (int h = ty; h < HID; h += 8)
            p = fmaf(W2[h], g_hxT[(size_t)h * NN + n], p);
    }
    red[ty][tx] = p;
    __syncthreads();
    if (ty == 0) {
        float s = red[0][tx];
        #pragma unroll
        for (int k = 1; k < 8; k++) s += red[k][tx];
        if (mode == 0)      g_t0[n] = softplus_f(s + b2[0]);
        else if (mode == 1) g_Ai[n] = s;
        else                g_Cj[n] = s;
    }
}

// ---------------------------------------------------------------------------
// Pair: S_abs[i][j] = sum_h w_h * |a_hi + c_hj|
// t1 = softplus(0.5*(A_i + C_j + S_abs) + b2)
// 64x64 tile, 16x16 threads, 4x4 micro-tile, f32x2 packed math.
// ---------------------------------------------------------------------------
__global__ void pair_kernel(const float* __restrict__ b2) {
    __shared__ ull   sA2[16][64];   // duplicated a (i side)
    __shared__ float sC[16][64];    // plain c (j side)
    __shared__ ull   sw2[16];

    const int i0 = blockIdx.y * 64;
    const int j0 = blockIdx.x * 64;
    const int tx = threadIdx.x, ty = threadIdx.y;
    const int tid = ty * 16 + tx;
    const int lr = tid >> 4;          // 0..15 (h row)
    const int lc = (tid & 15) * 4;    // 0..60

    ull acc2[4][2] = {};

    for (int h0 = 0; h0 < HP; h0 += 16) {
        {
            const ull* gsrc = &g_aT2[(size_t)(h0 + lr) * NN + i0 + lc];
            *(ulonglong2*)&sA2[lr][lc]     = *(const ulonglong2*)gsrc;
            *(ulonglong2*)&sA2[lr][lc + 2] = *(const ulonglong2*)(gsrc + 2);
            *(float4*)&sC[lr][lc] = *(const float4*)&g_hxT[(size_t)(h0 + lr) * NN + j0 + lc];
            if (tid < 16) sw2[tid] = g_w2dup[h0 + tid];
        }
        __syncthreads();

        #pragma unroll
        for (int hh = 0; hh < 16; hh++) {
            const ull w2v = sw2[hh];
            ulonglong2 av0 = *(const ulonglong2*)&sA2[hh][ty * 4];
            ulonglong2 av1 = *(const ulonglong2*)&sA2[hh][ty * 4 + 2];
            ulonglong2 cv  = *(const ulonglong2*)&sC[hh][tx * 4]; // {c0,c1},{c2,c3}
            ull a2[4] = {av0.x, av0.y, av1.x, av1.y};
            ull c2[2] = {cv.x, cv.y};
            #pragma unroll
            for (int p = 0; p < 4; p++) {
                #pragma unroll
                for (int q2 = 0; q2 < 2; q2++) {
                    ull v = add_f32x2(a2[p], c2[q2]);
                    v &= 0x7FFFFFFF7FFFFFFFULL;            // packed |.|
                    acc2[p][q2] = fma_f32x2(w2v, v, acc2[p][q2]);
                }
            }
        }
        __syncthreads();
    }

    const float bb = b2[0];
    float cj[4], ai[4];
    *(float4*)cj = *(const float4*)&g_Cj[j0 + tx * 4];
    *(float4*)ai = *(const float4*)&g_Ai[i0 + ty * 4];

    #pragma unroll
    for (int p = 0; p < 4; p++) {
        float s[4];
        s[0] = __uint_as_float((unsigned)(acc2[p][0] & 0xffffffffu));
        s[1] = __uint_as_float((unsigned)(acc2[p][0] >> 32));
        s[2] = __uint_as_float((unsigned)(acc2[p][1] & 0xffffffffu));
        s[3] = __uint_as_float((unsigned)(acc2[p][1] >> 32));
        float4 v;
        v.x = softplus_f(fmaf(0.5f, s[0] + ai[p] + cj[0], bb));
        v.y = softplus_f(fmaf(0.5f, s[1] + ai[p] + cj[1], bb));
        v.z = softplus_f(fmaf(0.5f, s[2] + ai[p] + cj[2], bb));
        v.w = softplus_f(fmaf(0.5f, s[3] + ai[p] + cj[3], bb));
        *(float4*)&g_t1[(size_t)(i0 + ty * 4 + p) * NN + j0 + tx * 4] = v;
    }
}

// ---------------------------------------------------------------------------
// Row logsumexp + final scalar (deterministic trees)
// ---------------------------------------------------------------------------
__global__ void lse_kernel() {
    __shared__ float red[256];
    const int i = blockIdx.x;
    const int t = threadIdx.x;
    const float* row = &g_t1[(size_t)i * NN];

    float m = -INFINITY;
    for (int j = t; j < NN; j += 256) m = fmaxf(m, row[j]);
    red[t] = m; __syncthreads();
    for (int s = 128; s > 0; s >>= 1) {
        if (t < s) red[t] = fmaxf(red[t], red[t + s]);
        __syncthreads();
    }
    m = red[0]; __syncthreads();

    float s = 0.f;
    for (int j = t; j < NN; j += 256) s += expf(row[j] - m);
    red[t] = s; __syncthreads();
    for (int st = 128; st > 0; st >>= 1) {
        if (t < st) red[t] += red[t + st];
        __syncthreads();
    }
    if (t == 0) g_lse[i] = m + logf(red[0]);
}

__global__ void final_kernel(float* __restrict__ out) {
    __shared__ float r0[256], r1[256];
    const int t = threadIdx.x;
    float s0 = 0.f, s1 = 0.f;
    for (int i = t; i < NN; i += 256) { s0 += g_t0[i]; s1 += g_lse[i]; }
    r0[t] = s0; r1[t] = s1; __syncthreads();
    for (int s = 128; s > 0; s >>= 1) {
        if (t < s) { r0[t] += r0[t + s]; r1[t] += r1[t + s]; }
        __syncthreads();
    }
    if (t == 0)
        out[0] = r0[0] / (float)NN - (r1[0] / (float)NN - logf((float)NN));
}

// ---------------------------------------------------------------------------
// Inputs: x_samples, y_samples, perm, W1, b1, W2, b2
// ---------------------------------------------------------------------------
extern "C" void kernel_launch(void* const* d_in, const int* in_sizes, int n_in,
                              void* d_out, int out_size) {
    const float* x    = (const float*)d_in[0];
    const float* y    = (const float*)d_in[1];
    const int*   perm = (const int*)d_in[2];
    const float* W1   = (const float*)d_in[3];
    const float* b1   = (const float*)d_in[4];
    const float* W2   = (const float*)d_in[5];
    const float* b2   = (const float*)d_in[6];
    float* out = (float*)d_out;

    dim3 blk(16, 16);
    dim3 ggrid(NN / 64, (HID + 63) / 64, 2);   // 12 x 5 x 2 = 120 CTAs
    gemm_hT<<<ggrid, blk>>>(x, y, W1);

    prep_kernel<<<(HP * NN + 255) / 256, 256>>>(perm, b1, W2);

    stats_kernel<<<dim3(NN / 32, 3), dim3(32, 8)>>>(b1, W2, b2);

    pair_kernel<<<dim3(NN / 64, NN / 64), blk>>>(b2);

    lse_kernel<<<NN, 256>>>();
    final_kernel<<<1, 256>>>(out);
}

// round 4
// speedup vs baseline: 1.7325x; 1.0846x over previous
#include <cuda_runtime.h>
#include <cuda_bf16.h>
#include <math.h>

#define NN 768
#define XD 768
#define HID 300
#define HP 304
#define W1COLS 1536

typedef unsigned long long ull;

// Scratch (device globals -- no allocation allowed)
__device__ float g_hxT[HP * NN];   // [h][n] hx^T ("c" side), rows >=300 zeroed
__device__ float g_hyT[HP * NN];   // [h][n] hy^T
__device__ float g_aT[HP * NN];    // [h][i] a = hy[perm i][h] + b1[h], pad rows zero
__device__ ull   g_w2dup[HP];      // {w,w}, 0 for h>=HID
__device__ float g_Ai[NN];         // sum_h w*a_hi
__device__ float g_Cj[NN];         // sum_h w*c_hj
__device__ float g_t1[NN * NN];    // softplus(t1)
__device__ float g_t0[NN];
__device__ float g_lse[NN];

__device__ __forceinline__ ull add_f32x2(ull a, ull b) {
    ull d; asm("add.rn.f32x2 %0, %1, %2;" : "=l"(d) : "l"(a), "l"(b)); return d;
}
__device__ __forceinline__ ull fma_f32x2(ull a, ull b, ull c) {
    ull d; asm("fma.rn.f32x2 %0, %1, %2, %3;" : "=l"(d) : "l"(a), "l"(b), "l"(c)); return d;
}
__device__ __forceinline__ ull dup_f32(float f) {
    ull d; unsigned u = __float_as_uint(f);
    asm("mov.b64 %0, {%1, %2};" : "=l"(d) : "r"(u), "r"(u)); return d;
}
__device__ __forceinline__ float lo_f(ull v) { return __uint_as_float((unsigned)(v & 0xffffffffu)); }
__device__ __forceinline__ float hi_f(ull v) { return __uint_as_float((unsigned)(v >> 32)); }
__device__ __forceinline__ float softplus_f(float z) {
    return fmaxf(z, 0.f) + log1pf(expf(-fabsf(z)));
}

// ---------------------------------------------------------------------------
// Fused GEMM: outT[h][n] = sum_k S[n][k] * W1[h][wofs+k]; z=0 -> hxT, z=1 -> hyT
// (unchanged from R2 -- known ~crossbar-bound; MMA replacement is next round)
// ---------------------------------------------------------------------------
__global__ void gemm_hT(const float* __restrict__ x, const float* __restrict__ y,
                        const float* __restrict__ W1) {
    __shared__ float sS[32][68];
    __shared__ float sW[32][68];

    const int which = blockIdx.z;
    const float* S = which ? y : x;
    const int wofs = which ? XD : 0;
    float* outT = which ? g_hyT : g_hxT;

    const int n0 = blockIdx.x * 64;
    const int h0 = blockIdx.y * 64;
    const int tx = threadIdx.x, ty = threadIdx.y;
    const int tid = ty * 16 + tx;
    const int lr = tid >> 3;
    const int lc = (tid & 7) * 4;

    float acc[4][4] = {};

    for (int k0 = 0; k0 < XD; k0 += 32) {
        {
            float4 v0 = *(const float4*)&S[(size_t)(n0 + lr) * XD + k0 + lc];
            float4 v1 = *(const float4*)&S[(size_t)(n0 + lr + 32) * XD + k0 + lc];
            sS[lc + 0][lr] = v0.x; sS[lc + 1][lr] = v0.y;
            sS[lc + 2][lr] = v0.z; sS[lc + 3][lr] = v0.w;
            sS[lc + 0][lr + 32] = v1.x; sS[lc + 1][lr + 32] = v1.y;
            sS[lc + 2][lr + 32] = v1.z; sS[lc + 3][lr + 32] = v1.w;
        }
        {
            const int h1 = h0 + lr, h2 = h0 + lr + 32;
            float4 v0 = make_float4(0.f, 0.f, 0.f, 0.f), v1 = v0;
            if (h1 < HID) v0 = *(const float4*)&W1[(size_t)h1 * W1COLS + wofs + k0 + lc];
            if (h2 < HID) v1 = *(const float4*)&W1[(size_t)h2 * W1COLS + wofs + k0 + lc];
            sW[lc + 0][lr] = v0.x; sW[lc + 1][lr] = v0.y;
            sW[lc + 2][lr] = v0.z; sW[lc + 3][lr] = v0.w;
            sW[lc + 0][lr + 32] = v1.x; sW[lc + 1][lr + 32] = v1.y;
            sW[lc + 2][lr + 32] = v1.z; sW[lc + 3][lr + 32] = v1.w;
        }
        __syncthreads();

        #pragma unroll
        for (int kk = 0; kk < 32; kk++) {
            float4 a4 = *(const float4*)&sW[kk][ty * 4];
            float4 b4 = *(const float4*)&sS[kk][tx * 4];
            float a[4] = {a4.x, a4.y, a4.z, a4.w};
            float b[4] = {b4.x, b4.y, b4.z, b4.w};
            #pragma unroll
            for (int p = 0; p < 4; p++)
                #pragma unroll
                for (int q = 0; q < 4; q++)
                    acc[p][q] = fmaf(a[p], b[q], acc[p][q]);
        }
        __syncthreads();
    }

    #pragma unroll
    for (int p = 0; p < 4; p++) {
        const int h = h0 + ty * 4 + p;
        if (h < HID) {
            float4 v = make_float4(acc[p][0], acc[p][1], acc[p][2], acc[p][3]);
            *(float4*)&outT[(size_t)h * NN + n0 + tx * 4] = v;
        }
    }
}

// ---------------------------------------------------------------------------
// mid_kernel: blocks 0..911 -> prep (aT, pads, w2dup); blocks 912..983 ->
// stats (mode 0: t0, 1: A_i from hyT+perm directly, 2: C_j). 256 thr each.
// No intra-kernel dependencies: everything reads only gemm outputs.
// ---------------------------------------------------------------------------
__global__ void mid_kernel(const int* __restrict__ perm,
                           const float* __restrict__ b1,
                           const float* __restrict__ W2,
                           const float* __restrict__ b2) {
    __shared__ float red[8][33];
    const int b = blockIdx.x;
    const int t = threadIdx.x;

    if (b < 912) {   // 912*256 == HP*NN exactly
        const int idx = b * 256 + t;
        const int h = idx / NN;
        const int i = idx - h * NN;
        if (h < HID) {
            g_aT[idx] = g_hyT[(size_t)h * NN + perm[i]] + b1[h];
        } else {
            g_aT[idx] = 0.f;
            g_hxT[idx] = 0.f;
        }
        if (idx < HP) {
            float w = (idx < HID) ? W2[idx] : 0.f;
            unsigned wb = __float_as_uint(w);
            g_w2dup[idx] = ((ull)wb << 32) | (ull)wb;
        }
        return;
    }

    const int bs = b - 912;          // 0..71
    const int mode = bs / 24;        // 24 blocks per mode
    const int tx = t & 31, ty = t >> 5;
    const int n = (bs % 24) * 32 + tx;

    float p = 0.f;
    if (mode == 0) {
        for (int h = ty; h < HID; h += 8) {
            float v = g_hxT[(size_t)h * NN + n] + g_hyT[(size_t)h * NN + n] + b1[h];
            p = fmaf(W2[h], fmaxf(v, 0.f), p);
        }
    } else if (mode == 1) {
        const int pi = perm[n];
        for (int h = ty; h < HID; h += 8)
            p = fmaf(W2[h], g_hyT[(size_t)h * NN + pi] + b1[h], p);
    } else {
        for (int h = ty; h < HID; h += 8)
            p = fmaf(W2[h], g_hxT[(size_t)h * NN + n], p);
    }
    red[ty][tx] = p;
    __syncthreads();
    if (ty == 0) {
        float s = red[0][tx];
        #pragma unroll
        for (int k = 1; k < 8; k++) s += red[k][tx];
        if (mode == 0)      g_t0[n] = softplus_f(s + b2[0]);
        else if (mode == 1) g_Ai[n] = s;
        else                g_Cj[n] = s;
    }
}

// ---------------------------------------------------------------------------
// Pair v3: 512 threads, 2-way in-CTA h-split (subgroup g=threadIdx.y).
// S_abs[i][j] = sum_h w_h*|a_hi + c_hj|;  t1 = softplus(0.5*(Ai+Cj+S)+b2).
// Accs packed over i-pairs: a operand pairs come free from LDS.128;
// c is dup'ed in registers. Subgroups sync with named barriers (different
// trip counts: 10 vs 9 chunks), combine partials in smem at the end.
// ---------------------------------------------------------------------------
__global__ void __launch_bounds__(512, 1) pair_kernel(const float* __restrict__ b2) {
    __shared__ float sA[2][16][64];
    __shared__ float sC[2][16][64];
    __shared__ ull   sw2s[2][16];
    __shared__ ull   cbuf[256][8];

    const int g  = threadIdx.y;        // 0 or 1
    const int t  = threadIdx.x;        // 0..255
    const int tx = t & 15;             // j quad
    const int ty = t >> 4;             // i quad
    const int i0 = blockIdx.y * 64;
    const int j0 = blockIdx.x * 64;
    const int lr = t >> 4;             // loader row 0..15
    const int lc = (t & 15) * 4;       // loader col

    const int c0 = g ? 10 : 0;
    const int c1 = g ? 19 : 10;        // 19 chunks total (HP=304)

    ull acc[2][4] = {};                // [i-pair][j]

    for (int ch = c0; ch < c1; ch++) {
        const int h0 = ch * 16;
        *(float4*)&sA[g][lr][lc] = *(const float4*)&g_aT[(size_t)(h0 + lr) * NN + i0 + lc];
        *(float4*)&sC[g][lr][lc] = *(const float4*)&g_hxT[(size_t)(h0 + lr) * NN + j0 + lc];
        if (t < 16) sw2s[g][t] = g_w2dup[h0 + t];
        asm volatile("bar.sync %0, 256;" :: "r"(g + 1) : "memory");

        #pragma unroll
        for (int hh = 0; hh < 16; hh++) {
            const ull wv = sw2s[g][hh];
            ulonglong2 pa = *(const ulonglong2*)&sA[g][hh][ty * 4]; // {a0,a1},{a2,a3}
            float4 c4 = *(const float4*)&sC[g][hh][tx * 4];
            ull pa2[2] = {pa.x, pa.y};
            ull cd[4] = {dup_f32(c4.x), dup_f32(c4.y), dup_f32(c4.z), dup_f32(c4.w)};
            #pragma unroll
            for (int p2 = 0; p2 < 2; p2++) {
                #pragma unroll
                for (int q = 0; q < 4; q++) {
                    ull v = add_f32x2(pa2[p2], cd[q]);
                    v &= 0x7FFFFFFF7FFFFFFFULL;          // packed |.|
                    acc[p2][q] = fma_f32x2(wv, v, acc[p2][q]);
                }
            }
        }
        asm volatile("bar.sync %0, 256;" :: "r"(g + 1) : "memory");
    }

    // Combine subgroup partials
    if (g == 1) {
        #pragma unroll
        for (int p2 = 0; p2 < 2; p2++)
            #pragma unroll
            for (int q = 0; q < 4; q++)
                cbuf[t][p2 * 4 + q] = acc[p2][q];
    }
    __syncthreads();
    if (g == 0) {
        #pragma unroll
        for (int p2 = 0; p2 < 2; p2++)
            #pragma unroll
            for (int q = 0; q < 4; q++)
                acc[p2][q] = add_f32x2(acc[p2][q], cbuf[t][p2 * 4 + q]);

        const float bb = b2[0];
        float cj[4], ai[4];
        *(float4*)cj = *(const float4*)&g_Cj[j0 + tx * 4];
        *(float4*)ai = *(const float4*)&g_Ai[i0 + ty * 4];

        #pragma unroll
        for (int p2 = 0; p2 < 2; p2++) {
            float4 vlo, vhi;
            vlo.x = softplus_f(fmaf(0.5f, lo_f(acc[p2][0]) + ai[2*p2]     + cj[0], bb));
            vlo.y = softplus_f(fmaf(0.5f, lo_f(acc[p2][1]) + ai[2*p2]     + cj[1], bb));
            vlo.z = softplus_f(fmaf(0.5f, lo_f(acc[p2][2]) + ai[2*p2]     + cj[2], bb));
            vlo.w = softplus_f(fmaf(0.5f, lo_f(acc[p2][3]) + ai[2*p2]     + cj[3], bb));
            vhi.x = softplus_f(fmaf(0.5f, hi_f(acc[p2][0]) + ai[2*p2 + 1] + cj[0], bb));
            vhi.y = softplus_f(fmaf(0.5f, hi_f(acc[p2][1]) + ai[2*p2 + 1] + cj[1], bb));
            vhi.z = softplus_f(fmaf(0.5f, hi_f(acc[p2][2]) + ai[2*p2 + 1] + cj[2], bb));
            vhi.w = softplus_f(fmaf(0.5f, hi_f(acc[p2][3]) + ai[2*p2 + 1] + cj[3], bb));
            *(float4*)&g_t1[(size_t)(i0 + ty * 4 + 2*p2)     * NN + j0 + tx * 4] = vlo;
            *(float4*)&g_t1[(size_t)(i0 + ty * 4 + 2*p2 + 1) * NN + j0 + tx * 4] = vhi;
        }
    }
}

// ---------------------------------------------------------------------------
// Row logsumexp + final scalar (deterministic trees)
// ---------------------------------------------------------------------------
__global__ void lse_kernel() {
    __shared__ float red[256];
    const int i = blockIdx.x;
    const int t = threadIdx.x;
    const float* row = &g_t1[(size_t)i * NN];

    float m = -INFINITY;
    for (int j = t; j < NN; j += 256) m = fmaxf(m, row[j]);
    red[t] = m; __syncthreads();
    for (int s = 128; s > 0; s >>= 1) {
        if (t < s) red[t] = fmaxf(red[t], red[t + s]);
        __syncthreads();
    }
    m = red[0]; __syncthreads();

    float s = 0.f;
    for (int j = t; j < NN; j += 256) s += expf(row[j] - m);
    red[t] = s; __syncthreads();
    for (int st = 128; st > 0; st >>= 1) {
        if (t < st) red[t] += red[t + st];
        __syncthreads();
    }
    if (t == 0) g_lse[i] = m + logf(red[0]);
}

__global__ void final_kernel(float* __restrict__ out) {
    __shared__ float r0[256], r1[256];
    const int t = threadIdx.x;
    float s0 = 0.f, s1 = 0.f;
    for (int i = t; i < NN; i += 256) { s0 += g_t0[i]; s1 += g_lse[i]; }
    r0[t] = s0; r1[t] = s1; __syncthreads();
    for (int s = 128; s > 0; s >>= 1) {
        if (t < s) { r0[t] += r0[t + s]; r1[t] += r1[t + s]; }
        __syncthreads();
    }
    if (t == 0)
        out[0] = r0[0] / (float)NN - (r1[0] / (float)NN - logf((float)NN));
}

// ---------------------------------------------------------------------------
// Inputs: x_samples, y_samples, perm, W1, b1, W2, b2
// ---------------------------------------------------------------------------
extern "C" void kernel_launch(void* const* d_in, const int* in_sizes, int n_in,
                              void* d_out, int out_size) {
    const float* x    = (const float*)d_in[0];
    const float* y    = (const float*)d_in[1];
    const int*   perm = (const int*)d_in[2];
    const float* W1   = (const float*)d_in[3];
    const float* b1   = (const float*)d_in[4];
    const float* W2   = (const float*)d_in[5];
    const float* b2   = (const float*)d_in[6];
    float* out = (float*)d_out;

    dim3 blk(16, 16);
    dim3 ggrid(NN / 64, (HID + 63) / 64, 2);   // 12 x 5 x 2 = 120 CTAs
    gemm_hT<<<ggrid, blk>>>(x, y, W1);

    mid_kernel<<<984, 256>>>(perm, b1, W2, b2);

    pair_kernel<<<dim3(NN / 64, NN / 64), dim3(256, 2)>>>(b2);

    lse_kernel<<<NN, 256>>>();
    final_kernel<<<1, 256>>>(out);
}